// round 1
// baseline (speedup 1.0000x reference)
#include <cuda_runtime.h>

#define NN 100000
#define NE 1600000
#define F_IN 128
#define F_HID 64
#define N_CLS 16

// ---------------- device scratch (static: no allocations allowed) ----------------
__device__ float g_t[NN * F_HID];     // t = act @ W  (gather source)
__device__ float g_h[NN * F_HID];     // aggregated activations
__device__ float g_dinv[NN];          // deg^{-1/2} (deg includes self loop)
__device__ int   g_deg[NN];           // in-edge count (excl. self loop)
__device__ int   g_off[NN];           // exclusive prefix of g_deg
__device__ int   g_cur[NN];           // bucket cursors
__device__ int   g_srcs[NE];          // src ids sorted by dst
__device__ float g_wsrc[NE];          // dinv[src] aligned with g_srcs
__device__ int   g_bsum[128];         // scan block sums (98 blocks)

// ---------------- CSR build ----------------
__global__ void k_init() {
    int i = blockIdx.x * blockDim.x + threadIdx.x;
    if (i < NN) { g_deg[i] = 0; g_cur[i] = 0; }
}

__global__ void k_count(const int* __restrict__ dst) {
    int i = blockIdx.x * blockDim.x + threadIdx.x;
    if (i < NE) atomicAdd(&g_deg[dst[i]], 1);
}

__global__ void k_scan1() {
    __shared__ int sh[1024];
    int i = blockIdx.x * 1024 + threadIdx.x;
    int v = (i < NN) ? g_deg[i] : 0;
    sh[threadIdx.x] = v;
    __syncthreads();
    #pragma unroll
    for (int ofs = 1; ofs < 1024; ofs <<= 1) {
        int t = (threadIdx.x >= ofs) ? sh[threadIdx.x - ofs] : 0;
        __syncthreads();
        sh[threadIdx.x] += t;
        __syncthreads();
    }
    if (i < NN) g_off[i] = sh[threadIdx.x] - v;            // exclusive
    if (threadIdx.x == 1023) g_bsum[blockIdx.x] = sh[1023]; // block total
}

__global__ void k_scan2(int nb) {
    if (threadIdx.x == 0) {
        int run = 0;
        for (int b = 0; b < nb; b++) { int t = g_bsum[b]; g_bsum[b] = run; run += t; }
    }
}

__global__ void k_scan3_dinv() {
    int i = blockIdx.x * blockDim.x + threadIdx.x;
    if (i < NN) {
        g_off[i] += g_bsum[i >> 10];
        g_dinv[i] = rsqrtf((float)(g_deg[i] + 1));   // +1 self loop; always > 0
    }
}

__global__ void k_fill(const int* __restrict__ src, const int* __restrict__ dst) {
    int i = blockIdx.x * blockDim.x + threadIdx.x;
    if (i < NE) {
        int d = dst[i];
        int s = src[i];
        int p = atomicAdd(&g_cur[d], 1);
        int slot = g_off[d] + p;
        g_srcs[slot] = s;
        g_wsrc[slot] = g_dinv[s];
    }
}

// ---------------- GEMM: C[n,64] = A[n,K] @ W[K,64], 256-node x 64-col tile,
// ---------------- 8x8 register micro-tile per thread (1 B LDS per FMA) ----------------
template<int K, bool USE_GH>
__global__ __launch_bounds__(256, 2) void k_gemm64(const float* __restrict__ Aext,
                                                   const float* __restrict__ W) {
    const int KC = 16;
    const int XS_STRIDE = 260;                 // pad: keep 16B alignment, break bank conflicts
    __shared__ float Xs[KC * XS_STRIDE];
    __shared__ float Ws[KC * 64];

    const float* __restrict__ A = USE_GH ? (const float*)g_h : Aext;

    int tid = threadIdx.x;
    int tx = tid & 7;          // col group: cols tx*8 .. tx*8+7
    int ty = tid >> 3;         // node group: nodes ty*8 .. ty*8+7 (0..31)
    int nb = blockIdx.x * 256;

    float acc[8][8];
    #pragma unroll
    for (int i = 0; i < 8; i++)
        #pragma unroll
        for (int j = 0; j < 8; j++) acc[i][j] = 0.f;

    for (int k0 = 0; k0 < K; k0 += KC) {
        // fill Xs transposed: Xs[kk][node]
        {
            int kk = (tid & 3) * 4;
            #pragma unroll
            for (int r = 0; r < 4; r++) {
                int node = r * 64 + (tid >> 2);
                float4 v = make_float4(0.f, 0.f, 0.f, 0.f);
                int gn = nb + node;
                if (gn < NN) v = *(const float4*)(A + (long)gn * K + k0 + kk);
                Xs[(kk + 0) * XS_STRIDE + node] = v.x;
                Xs[(kk + 1) * XS_STRIDE + node] = v.y;
                Xs[(kk + 2) * XS_STRIDE + node] = v.z;
                Xs[(kk + 3) * XS_STRIDE + node] = v.w;
            }
            int kk2 = tid >> 4;                // 0..15
            int c = (tid & 15) * 4;            // 0..60
            *(float4*)(Ws + kk2 * 64 + c) = *(const float4*)(W + (k0 + kk2) * 64 + c);
        }
        __syncthreads();

        #pragma unroll
        for (int kk = 0; kk < KC; kk++) {
            float4 a0 = *(const float4*)(Xs + kk * XS_STRIDE + ty * 8);
            float4 a1 = *(const float4*)(Xs + kk * XS_STRIDE + ty * 8 + 4);
            float4 b0 = *(const float4*)(Ws + kk * 64 + tx * 8);
            float4 b1 = *(const float4*)(Ws + kk * 64 + tx * 8 + 4);
            float a[8] = {a0.x, a0.y, a0.z, a0.w, a1.x, a1.y, a1.z, a1.w};
            float b[8] = {b0.x, b0.y, b0.z, b0.w, b1.x, b1.y, b1.z, b1.w};
            #pragma unroll
            for (int i = 0; i < 8; i++)
                #pragma unroll
                for (int j = 0; j < 8; j++)
                    acc[i][j] = fmaf(a[i], b[j], acc[i][j]);
        }
        __syncthreads();
    }

    #pragma unroll
    for (int i = 0; i < 8; i++) {
        int gn = nb + ty * 8 + i;
        if (gn < NN) {
            float4 o0 = make_float4(acc[i][0], acc[i][1], acc[i][2], acc[i][3]);
            float4 o1 = make_float4(acc[i][4], acc[i][5], acc[i][6], acc[i][7]);
            *(float4*)(g_t + (long)gn * 64 + tx * 8)     = o0;
            *(float4*)(g_t + (long)gn * 64 + tx * 8 + 4) = o1;
        }
    }
}

// ---------------- Aggregation: warp per node, float2 per lane ----------------
// h[node] = relu?( bias + dinv_i * ( sum_s dinv_s * t[s] + dinv_i * t[node] ) )
__global__ void k_agg(const float* __restrict__ bias, int relu) {
    int wid  = (blockIdx.x * blockDim.x + threadIdx.x) >> 5;
    int lane = threadIdx.x & 31;
    if (wid >= NN) return;
    int node = wid;

    const float2* __restrict__ tp = (const float2*)g_t;
    float2 acc = make_float2(0.f, 0.f);

    int row = g_off[node];
    int cnt = g_deg[node];

    for (int base = 0; base < cnt; base += 32) {
        int idx = base + lane;
        int s = 0; float dv = 0.f;
        if (idx < cnt) { s = g_srcs[row + idx]; dv = g_wsrc[row + idx]; }
        int m = min(32, cnt - base);
        #pragma unroll 4
        for (int j = 0; j < m; j++) {
            int   sj = __shfl_sync(0xffffffffu, s,  j);
            float wj = __shfl_sync(0xffffffffu, dv, j);
            float2 tv = tp[(long)sj * 32 + lane];
            acc.x = fmaf(wj, tv.x, acc.x);
            acc.y = fmaf(wj, tv.y, acc.y);
        }
    }

    float  di = g_dinv[node];
    float2 ts = tp[(long)node * 32 + lane];
    float2 bv = ((const float2*)bias)[lane];
    float ox = (acc.x + di * ts.x) * di + bv.x;
    float oy = (acc.y + di * ts.y) * di + bv.y;
    if (relu) { ox = fmaxf(ox, 0.f); oy = fmaxf(oy, 0.f); }
    ((float2*)g_h)[(long)node * 32 + lane] = make_float2(ox, oy);
}

// ---------------- Final: out[n,16] = g_h[n,64] @ Wc[64,16] + bc ----------------
__global__ void k_final(const float* __restrict__ Wc, const float* __restrict__ bc,
                        float* __restrict__ out) {
    __shared__ float Ws[F_HID * N_CLS];   // 64x16
    int tid = threadIdx.x;
    for (int i = tid; i < F_HID * N_CLS; i += 256) Ws[i] = Wc[i];
    __syncthreads();

    int node = blockIdx.x * 64 + (tid >> 2);
    if (node >= NN) return;
    int c4 = (tid & 3) * 4;

    float4 acc = *(const float4*)(bc + c4);
    const float* __restrict__ hp = g_h + (long)node * 64;
    #pragma unroll
    for (int k = 0; k < 64; k++) {
        float hv = __ldg(hp + k);
        float4 w = *(const float4*)(Ws + k * 16 + c4);
        acc.x = fmaf(hv, w.x, acc.x);
        acc.y = fmaf(hv, w.y, acc.y);
        acc.z = fmaf(hv, w.z, acc.z);
        acc.w = fmaf(hv, w.w, acc.w);
    }
    *(float4*)(out + (long)node * 16 + c4) = acc;
}

// ---------------- launch ----------------
extern "C" void kernel_launch(void* const* d_in, const int* in_sizes, int n_in,
                              void* d_out, int out_size) {
    (void)in_sizes; (void)n_in; (void)out_size;
    const float* x  = (const float*)d_in[0];
    const int*   ei = (const int*)d_in[1];
    const float* W0 = (const float*)d_in[2];
    const float* b0 = (const float*)d_in[3];
    const float* W1 = (const float*)d_in[4];
    const float* b1 = (const float*)d_in[5];
    const float* W2 = (const float*)d_in[6];
    const float* b2 = (const float*)d_in[7];
    const float* Wc = (const float*)d_in[8];
    const float* bc = (const float*)d_in[9];
    float* out = (float*)d_out;

    const int* src = ei;            // edge_index[0]
    const int* dst = ei + NE;       // edge_index[1]

    int nbN  = (NN + 255) / 256;            // 391
    int nbE  = (NE + 255) / 256;            // 6250
    int nbS  = (NN + 1023) / 1024;          // 98
    int nbG  = (NN + 255) / 256;            // 391 (256-node gemm tiles)
    int nbA  = NN / 8;                      // 12500 (8 warps/block, exact)
    int nbF  = (NN + 63) / 64;              // 1563

    // CSR build + normalization (recomputed every replay: buffers are persistent)
    k_init<<<nbN, 256>>>();
    k_count<<<nbE, 256>>>(dst);
    k_scan1<<<nbS, 1024>>>();
    k_scan2<<<1, 32>>>(nbS);
    k_scan3_dinv<<<nbN, 256>>>();
    k_fill<<<nbE, 256>>>(src, dst);

    // layer 0
    k_gemm64<F_IN, false><<<nbG, 256>>>(x, W0);
    k_agg<<<nbA, 256>>>(b0, 1);
    // layer 1
    k_gemm64<F_HID, true><<<nbG, 256>>>(nullptr, W1);
    k_agg<<<nbA, 256>>>(b1, 1);
    // layer 2
    k_gemm64<F_HID, true><<<nbG, 256>>>(nullptr, W2);
    k_agg<<<nbA, 256>>>(b2, 0);
    // classifier
    k_final<<<nbF, 256>>>(Wc, bc, out);
}

// round 3
// speedup vs baseline: 1.2282x; 1.2282x over previous
#include <cuda_runtime.h>
#include <cuda_fp16.h>

#define NN 100000
#define NE 1600000
#define F_IN 128
#define F_HID 64
#define N_CLS 16

// ---------------- device scratch (static: no allocations allowed) ----------------
__device__ __half2 g_t[NN * 32];      // t = act @ W  (gather source, fp16, 64 vals/row)
__device__ float   g_h[NN * F_HID];   // aggregated activations (fp32)
__device__ float   g_dinv[NN];        // deg^{-1/2} (deg includes self loop)
__device__ int     g_deg[NN];         // in-edge count (excl. self loop)
__device__ int     g_off[NN];         // exclusive prefix of g_deg
__device__ int     g_cur[NN];         // bucket cursors
__device__ int2    g_epk[NE];         // packed (src, __float_as_int(dinv[src])) by dst bucket
__device__ int     g_bsum[128];       // scan block sums (98 blocks)

// ---------------- f32x2 helpers (Blackwell packed fp32 FMA) ----------------
__device__ __forceinline__ void ffma2(unsigned long long& d,
                                      unsigned long long a, unsigned long long b) {
    asm("fma.rn.f32x2 %0, %1, %2, %3;" : "=l"(d) : "l"(a), "l"(b), "l"(d));
}
__device__ __forceinline__ unsigned long long packdup(float a) {
    unsigned long long r;
    asm("mov.b64 %0, {%1, %1};" : "=l"(r) : "f"(a));
    return r;
}
__device__ __forceinline__ float2 unpk64(unsigned long long v) {
    float2 f;
    asm("mov.b64 {%0, %1}, %2;" : "=f"(f.x), "=f"(f.y) : "l"(v));
    return f;
}

// ---------------- CSR build ----------------
__global__ void k_init() {
    int i = blockIdx.x * blockDim.x + threadIdx.x;
    if (i < NN) { g_deg[i] = 0; g_cur[i] = 0; }
}

__global__ void k_count(const int* __restrict__ dst) {
    int i = blockIdx.x * blockDim.x + threadIdx.x;
    if (i < NE) atomicAdd(&g_deg[dst[i]], 1);
}

__global__ void k_scan1() {
    __shared__ int sh[1024];
    int i = blockIdx.x * 1024 + threadIdx.x;
    int v = (i < NN) ? g_deg[i] : 0;
    sh[threadIdx.x] = v;
    __syncthreads();
    #pragma unroll
    for (int ofs = 1; ofs < 1024; ofs <<= 1) {
        int t = (threadIdx.x >= ofs) ? sh[threadIdx.x - ofs] : 0;
        __syncthreads();
        sh[threadIdx.x] += t;
        __syncthreads();
    }
    if (i < NN) g_off[i] = sh[threadIdx.x] - v;             // exclusive
    if (threadIdx.x == 1023) g_bsum[blockIdx.x] = sh[1023]; // block total
}

// parallel scan of the 98 block sums (1 block, 128 threads)
__global__ void k_scan2(int nb) {
    int t = threadIdx.x;
    int lane = t & 31, w = t >> 5;
    int v = (t < nb) ? g_bsum[t] : 0;
    int x = v;
    #pragma unroll
    for (int o = 1; o < 32; o <<= 1) {
        int y = __shfl_up_sync(0xffffffffu, x, o);
        if (lane >= o) x += y;
    }
    __shared__ int wt[4];
    if (lane == 31) wt[w] = x;
    __syncthreads();
    int add = 0;
    #pragma unroll
    for (int i = 0; i < 4; i++) if (i < w) add += wt[i];
    x += add;
    if (t < nb) g_bsum[t] = x - v;   // exclusive
}

__global__ void k_scan3_dinv() {
    int i = blockIdx.x * blockDim.x + threadIdx.x;
    if (i < NN) {
        g_off[i] += g_bsum[i >> 10];
        g_dinv[i] = rsqrtf((float)(g_deg[i] + 1));   // +1 self loop; always > 0
    }
}

__global__ void k_fill(const int* __restrict__ src, const int* __restrict__ dst) {
    int i = blockIdx.x * blockDim.x + threadIdx.x;
    if (i < NE) {
        int d = dst[i];
        int s = src[i];
        int p = atomicAdd(&g_cur[d], 1);
        g_epk[g_off[d] + p] = make_int2(s, __float_as_int(g_dinv[s]));
    }
}

// ---------------- GEMM: g_t[n,64](fp16) = A[n,K] @ W[K,64], FFMA2 inner loop ----------------
template<int K, bool USE_GH>
__global__ __launch_bounds__(256, 2) void k_gemm64(const float* __restrict__ Aext,
                                                   const float* __restrict__ W) {
    const int KC = 16;
    const int XS_STRIDE = 260;
    __shared__ float Xs[KC * XS_STRIDE];
    __shared__ float Ws[KC * 64];

    const float* __restrict__ A = USE_GH ? (const float*)g_h : Aext;

    int tid = threadIdx.x;
    int tx = tid & 7;          // col group: cols tx*8 .. tx*8+7
    int ty = tid >> 3;         // node group: nodes ty*8 .. ty*8+7
    int nb = blockIdx.x * 256;

    unsigned long long accp[8][4];
    #pragma unroll
    for (int i = 0; i < 8; i++)
        #pragma unroll
        for (int j = 0; j < 4; j++) accp[i][j] = 0ull;

    for (int k0 = 0; k0 < K; k0 += KC) {
        {
            int kk = (tid & 3) * 4;
            #pragma unroll
            for (int r = 0; r < 4; r++) {
                int node = r * 64 + (tid >> 2);
                float4 v = make_float4(0.f, 0.f, 0.f, 0.f);
                int gn = nb + node;
                if (gn < NN) v = *(const float4*)(A + (long)gn * K + k0 + kk);
                Xs[(kk + 0) * XS_STRIDE + node] = v.x;
                Xs[(kk + 1) * XS_STRIDE + node] = v.y;
                Xs[(kk + 2) * XS_STRIDE + node] = v.z;
                Xs[(kk + 3) * XS_STRIDE + node] = v.w;
            }
            int kk2 = tid >> 4;
            int c = (tid & 15) * 4;
            *(float4*)(Ws + kk2 * 64 + c) = *(const float4*)(W + (k0 + kk2) * 64 + c);
        }
        __syncthreads();

        #pragma unroll
        for (int kk = 0; kk < KC; kk++) {
            float4 a0 = *(const float4*)(Xs + kk * XS_STRIDE + ty * 8);
            float4 a1 = *(const float4*)(Xs + kk * XS_STRIDE + ty * 8 + 4);
            // B column pairs come straight from memory layout as u64 lanes
            ulonglong2 w0 = *(const ulonglong2*)(Ws + kk * 64 + tx * 8);
            ulonglong2 w1 = *(const ulonglong2*)(Ws + kk * 64 + tx * 8 + 4);
            unsigned long long bp[4] = {w0.x, w0.y, w1.x, w1.y};
            float a[8] = {a0.x, a0.y, a0.z, a0.w, a1.x, a1.y, a1.z, a1.w};
            #pragma unroll
            for (int i = 0; i < 8; i++) {
                unsigned long long ad = packdup(a[i]);
                #pragma unroll
                for (int j = 0; j < 4; j++)
                    ffma2(accp[i][j], ad, bp[j]);
            }
        }
        __syncthreads();
    }

    #pragma unroll
    for (int i = 0; i < 8; i++) {
        int gn = nb + ty * 8 + i;
        if (gn < NN) {
            __half2 hh[4];
            #pragma unroll
            for (int j = 0; j < 4; j++) {
                float2 f = unpk64(accp[i][j]);
                hh[j] = __floats2half2_rn(f.x, f.y);
            }
            *(uint4*)(g_t + (long)gn * 32 + tx * 4) = *(uint4*)hh;
        }
    }
}

// ---------------- Aggregation: warp per node, half2 gather, fp32 accumulate ----------------
// h[node] = act( bias + dinv_i * ( sum_s dinv_s * t[s] + dinv_i * t[node] ) )
// FINAL: fuse classifier out[node,16] = h @ Wc + bc (no relu, no g_h write)
template<int RELU, int FINAL>
__global__ __launch_bounds__(256) void k_agg(const float* __restrict__ bias,
                                             const float* __restrict__ Wc,
                                             const float* __restrict__ bc,
                                             float* __restrict__ out) {
    __shared__ float Wcs[F_HID * N_CLS];   // only used when FINAL
    __shared__ float hs[8][F_HID];
    if (FINAL) {
        for (int i = threadIdx.x; i < F_HID * N_CLS; i += 256) Wcs[i] = Wc[i];
        __syncthreads();
    }

    int w    = threadIdx.x >> 5;
    int lane = threadIdx.x & 31;
    int node = blockIdx.x * 8 + w;      // grid is exact: NN/8 blocks

    const __half2* __restrict__ tp = g_t;
    float2 acc = make_float2(0.f, 0.f);

    int row = g_off[node];
    int cnt = g_deg[node];

    for (int base = 0; base < cnt; base += 32) {
        int idx = base + lane;
        int2 e = make_int2(0, 0);                      // e.y == 0.0f bits
        if (idx < cnt) e = g_epk[row + idx];
        int m = min(32, cnt - base);
        if (m == 32) {
            #pragma unroll
            for (int j = 0; j < 32; j++) {
                int   sj = __shfl_sync(0xffffffffu, e.x, j);
                float wj = __int_as_float(__shfl_sync(0xffffffffu, e.y, j));
                float2 tv = __half22float2(tp[(long)sj * 32 + lane]);
                acc.x = fmaf(wj, tv.x, acc.x);
                acc.y = fmaf(wj, tv.y, acc.y);
            }
        } else {
            #pragma unroll 4
            for (int j = 0; j < m; j++) {
                int   sj = __shfl_sync(0xffffffffu, e.x, j);
                float wj = __int_as_float(__shfl_sync(0xffffffffu, e.y, j));
                float2 tv = __half22float2(tp[(long)sj * 32 + lane]);
                acc.x = fmaf(wj, tv.x, acc.x);
                acc.y = fmaf(wj, tv.y, acc.y);
            }
        }
    }

    float  di = g_dinv[node];
    float2 ts = __half22float2(tp[(long)node * 32 + lane]);
    float2 bv = ((const float2*)bias)[lane];
    float ox = (acc.x + di * ts.x) * di + bv.x;
    float oy = (acc.y + di * ts.y) * di + bv.y;

    if (FINAL) {
        // classifier fused: h (64 floats across the warp) @ Wc[64,16] + bc
        hs[w][2 * lane]     = ox;
        hs[w][2 * lane + 1] = oy;
        __syncwarp();
        int c  = lane & 15;
        int k0 = (lane >> 4) * 32;
        float s = 0.f;
        #pragma unroll
        for (int k = 0; k < 32; k++)
            s = fmaf(hs[w][k0 + k], Wcs[(k0 + k) * N_CLS + c], s);
        s += __shfl_xor_sync(0xffffffffu, s, 16);
        if (lane < 16) out[(long)node * N_CLS + c] = s + __ldg(bc + c);
    } else {
        if (RELU) { ox = fmaxf(ox, 0.f); oy = fmaxf(oy, 0.f); }
        ((float2*)g_h)[(long)node * 32 + lane] = make_float2(ox, oy);
    }
}

// ---------------- launch ----------------
extern "C" void kernel_launch(void* const* d_in, const int* in_sizes, int n_in,
                              void* d_out, int out_size) {
    (void)in_sizes; (void)n_in; (void)out_size;
    const float* x  = (const float*)d_in[0];
    const int*   ei = (const int*)d_in[1];
    const float* W0 = (const float*)d_in[2];
    const float* b0 = (const float*)d_in[3];
    const float* W1 = (const float*)d_in[4];
    const float* b1 = (const float*)d_in[5];
    const float* W2 = (const float*)d_in[6];
    const float* b2 = (const float*)d_in[7];
    const float* Wc = (const float*)d_in[8];
    const float* bc = (const float*)d_in[9];
    float* out = (float*)d_out;

    const int* src = ei;            // edge_index[0]
    const int* dst = ei + NE;       // edge_index[1]

    int nbN = (NN + 255) / 256;     // 391
    int nbE = (NE + 255) / 256;     // 6250
    int nbS = (NN + 1023) / 1024;   // 98
    int nbG = (NN + 255) / 256;     // 391
    int nbA = NN / 8;               // 12500 (exact)

    // CSR build + normalization (replayed every graph launch)
    k_init<<<nbN, 256>>>();
    k_count<<<nbE, 256>>>(dst);
    k_scan1<<<nbS, 1024>>>();
    k_scan2<<<1, 128>>>(nbS);
    k_scan3_dinv<<<nbN, 256>>>();
    k_fill<<<nbE, 256>>>(src, dst);

    // layer 0
    k_gemm64<F_IN, false><<<nbG, 256>>>(x, W0);
    k_agg<1, 0><<<nbA, 256>>>(b0, nullptr, nullptr, nullptr);
    // layer 1
    k_gemm64<F_HID, true><<<nbG, 256>>>(nullptr, W1);
    k_agg<1, 0><<<nbA, 256>>>(b1, nullptr, nullptr, nullptr);
    // layer 2 + fused classifier
    k_gemm64<F_HID, true><<<nbG, 256>>>(nullptr, W2);
    k_agg<0, 1><<<nbA, 256>>>(b2, Wc, bc, out);
}